// round 1
// baseline (speedup 1.0000x reference)
#include <cuda_runtime.h>
#include <cstdint>
#include <cstring>

#define T_STEPS 2048
#define BATCH   8
#define DIMK    1024
#define NST     64
#define M_ROWS  (T_STEPS * BATCH)
#define NCOL    256

// 16 MB scratch: projections, layout [t*BATCH+b][ k(0:64) | q(64:128) | v(128:192) | alpha(192:256) ]
__device__ __align__(16) float g_proj[(size_t)M_ROWS * NCOL];

union F2U { float2 f2; unsigned long long u; };

__device__ __forceinline__ float2 f2fma(float2 a, float2 b, float2 c) {
    F2U ua, ub, uc, ud; ua.f2 = a; ub.f2 = b; uc.f2 = c;
    asm("fma.rn.f32x2 %0, %1, %2, %3;" : "=l"(ud.u) : "l"(ua.u), "l"(ub.u), "l"(uc.u));
    return ud.f2;
}
__device__ __forceinline__ float2 f2mul(float2 a, float2 b) {
    F2U ua, ub, ud; ua.f2 = a; ub.f2 = b;
    asm("mul.rn.f32x2 %0, %1, %2;" : "=l"(ud.u) : "l"(ua.u), "l"(ub.u));
    return ud.f2;
}
__device__ __forceinline__ float2 f2add(float2 a, float2 b) {
    F2U ua, ub, ud; ua.f2 = a; ub.f2 = b;
    asm("add.rn.f32x2 %0, %1, %2;" : "=l"(ud.u) : "l"(ua.u), "l"(ub.u));
    return ud.f2;
}
__device__ __forceinline__ float2 f2dup(float a) {
    F2U ud;
    asm("mov.b64 %0, {%1, %1};" : "=l"(ud.u) : "f"(a));
    return ud.f2;
}
__device__ __forceinline__ float sigmoidf_fast(float x) {
    return __fdividef(1.0f, 1.0f + __expf(-x));
}

// ============================================================================
// Kernel 1: fused projection GEMM. C[m][n] = sum_d x[m][d] * W_sel[n][d]
// blockIdx.y selects which weight matrix (0:k 1:q 2:v 3:alpha).
// ============================================================================
#define BM 128
#define BN 64
#define BK 16

__global__ void __launch_bounds__(256) proj_kernel(
    const float* __restrict__ x,
    const float* __restrict__ Wk, const float* __restrict__ Wq,
    const float* __restrict__ Wv, const float* __restrict__ Wa,
    const float* __restrict__ b_alpha)
{
    __shared__ __align__(16) float As[BK][BM + 4];
    __shared__ __align__(16) float Bs[BK][BN + 4];

    const int tid = threadIdx.x;
    const int m0  = blockIdx.x * BM;
    const int sel = blockIdx.y;
    const float* W = (sel == 0) ? Wk : (sel == 1) ? Wq : (sel == 2) ? Wv : Wa;

    const int ty = tid >> 4;         // 0..15 -> 8 rows each
    const int tx = tid & 15;         // 0..15 -> 4 cols each

    const int lrow = tid >> 2;       // 0..63
    const int lcol = (tid & 3) * 4;  // 0,4,8,12

    float2 acc[4][4];
    #pragma unroll
    for (int ip = 0; ip < 4; ip++)
        #pragma unroll
        for (int j = 0; j < 4; j++) acc[ip][j] = make_float2(0.f, 0.f);

    for (int k0 = 0; k0 < DIMK; k0 += BK) {
        #pragma unroll
        for (int half = 0; half < 2; half++) {
            int r = lrow + half * 64;
            float4 v = *reinterpret_cast<const float4*>(&x[(size_t)(m0 + r) * DIMK + k0 + lcol]);
            As[lcol + 0][r] = v.x; As[lcol + 1][r] = v.y;
            As[lcol + 2][r] = v.z; As[lcol + 3][r] = v.w;
        }
        {
            float4 v = *reinterpret_cast<const float4*>(&W[(size_t)lrow * DIMK + k0 + lcol]);
            Bs[lcol + 0][lrow] = v.x; Bs[lcol + 1][lrow] = v.y;
            Bs[lcol + 2][lrow] = v.z; Bs[lcol + 3][lrow] = v.w;
        }
        __syncthreads();
        #pragma unroll
        for (int k = 0; k < BK; k++) {
            float4 a0 = *reinterpret_cast<const float4*>(&As[k][ty * 8]);
            float4 a1 = *reinterpret_cast<const float4*>(&As[k][ty * 8 + 4]);
            float4 bv = *reinterpret_cast<const float4*>(&Bs[k][tx * 4]);
            float2 a2[4] = { make_float2(a0.x, a0.y), make_float2(a0.z, a0.w),
                             make_float2(a1.x, a1.y), make_float2(a1.z, a1.w) };
            float2 bd[4] = { f2dup(bv.x), f2dup(bv.y), f2dup(bv.z), f2dup(bv.w) };
            #pragma unroll
            for (int ip = 0; ip < 4; ip++)
                #pragma unroll
                for (int j = 0; j < 4; j++)
                    acc[ip][j] = f2fma(a2[ip], bd[j], acc[ip][j]);
        }
        __syncthreads();
    }

    // epilogue: rows ty*8 + 2*ip + h, cols tx*4 + j
    #pragma unroll
    for (int ip = 0; ip < 4; ip++) {
        #pragma unroll
        for (int h = 0; h < 2; h++) {
            int r = ty * 8 + ip * 2 + h;
            float4 o;
            o.x = h ? acc[ip][0].y : acc[ip][0].x;
            o.y = h ? acc[ip][1].y : acc[ip][1].x;
            o.z = h ? acc[ip][2].y : acc[ip][2].x;
            o.w = h ? acc[ip][3].y : acc[ip][3].x;
            if (sel == 3) {  // alpha = sigmoid(proj + b_alpha)
                o.x = sigmoidf_fast(o.x + b_alpha[tx * 4 + 0]);
                o.y = sigmoidf_fast(o.y + b_alpha[tx * 4 + 1]);
                o.z = sigmoidf_fast(o.z + b_alpha[tx * 4 + 2]);
                o.w = sigmoidf_fast(o.w + b_alpha[tx * 4 + 3]);
            }
            *reinterpret_cast<float4*>(&g_proj[(size_t)(m0 + r) * NCOL + sel * 64 + tx * 4]) = o;
        }
    }
}

// ============================================================================
// Kernel 2: sequential scan. Rows of S are independent: 512 row-recurrences.
// 4 lanes per row (16 state elems each as 8 x f32x2), 8 rows per warp,
// 64 warps = 64 blocks x 32 threads. Operands staged via cp.async ring.
// ============================================================================
#define DPF 8   // ring slots; DPF-1 groups in flight

__global__ void __launch_bounds__(32) scan_kernel(
    const float* __restrict__ S0,
    const float* __restrict__ d_g,
    const float* __restrict__ b_g,
    float* __restrict__ out,     // [T,B,N]
    float* __restrict__ Sfin)    // [B,N,N]
{
    __shared__ __align__(16) float buf[DPF][NCOL];

    const int w    = blockIdx.x;
    const int b    = w >> 3;
    const int gr   = w & 7;
    const int lane = threadIdx.x;
    const int r    = lane >> 2;
    const int c    = lane & 3;
    const int i    = gr * 8 + r;      // global row 0..63

    const float dg = d_g[i];
    const float bg = b_g[i];

    float2 s[8];
    {
        const float4* sp = reinterpret_cast<const float4*>(&S0[(size_t)(b * NST + i) * NST + c * 16]);
        #pragma unroll
        for (int m = 0; m < 4; m++) {
            float4 v = sp[m];
            s[2*m]   = make_float2(v.x, v.y);
            s[2*m+1] = make_float2(v.z, v.w);
        }
    }

    const int loff = lane * 4;
    const uint32_t sbase = (uint32_t)__cvta_generic_to_shared(&buf[0][0]);

    // prologue: fetch steps 0..DPF-2 into slots 0..DPF-2
    #pragma unroll
    for (int d = 0; d < DPF - 1; d++) {
        const float* src = &g_proj[((size_t)d * BATCH + b) * NCOL + loff];
        uint32_t sa = sbase + (uint32_t)(d * NCOL + loff) * 4u;
        asm volatile(
            "cp.async.ca.shared.global [%0], [%1], 16;\n\t"
            "cp.async.ca.shared.global [%2], [%3], 16;\n\t"
            :: "r"(sa), "l"(src), "r"(sa + 512u), "l"(src + 128));
        asm volatile("cp.async.commit_group;");
    }

    for (int t = 0; t < T_STEPS; t++) {
        asm volatile("cp.async.wait_group %0;" :: "n"(DPF - 2));
        __syncthreads();

        const float* p = &buf[t & (DPF - 1)][0];
        float2 kk[8], qq[8];
        {
            const float4* kp = reinterpret_cast<const float4*>(p + c * 16);
            const float4* qp = reinterpret_cast<const float4*>(p + 64 + c * 16);
            #pragma unroll
            for (int m = 0; m < 4; m++) {
                float4 v = kp[m];
                kk[2*m] = make_float2(v.x, v.y); kk[2*m+1] = make_float2(v.z, v.w);
                float4 u = qp[m];
                qq[2*m] = make_float2(u.x, u.y); qq[2*m+1] = make_float2(u.z, u.w);
            }
        }
        const float v_i = p[128 + i];
        const float a_i = p[192 + i];

        // prefetch step t+DPF-1 into slot (t-1)&(DPF-1); that slot's data was
        // fully consumed (its LDS results bound by the FMAs of iter t-1, which
        // precede this point in warp program order).
        {
            int tf = t + DPF - 1;
            if (tf > T_STEPS - 1) tf = T_STEPS - 1;
            int slot = tf & (DPF - 1);
            const float* src = &g_proj[((size_t)tf * BATCH + b) * NCOL + loff];
            uint32_t sa = sbase + (uint32_t)(slot * NCOL + loff) * 4u;
            asm volatile(
                "cp.async.ca.shared.global [%0], [%1], 16;\n\t"
                "cp.async.ca.shared.global [%2], [%3], 16;\n\t"
                :: "r"(sa), "l"(src), "r"(sa + 512u), "l"(src + 128));
            asm volatile("cp.async.commit_group;");
        }

        // retrieved_i = s . k   (partial per lane, butterfly over 4 lanes)
        float2 d0 = f2mul(s[0], kk[0]);
        float2 d1 = f2mul(s[1], kk[1]);
        float2 d2 = f2mul(s[2], kk[2]);
        float2 d3 = f2mul(s[3], kk[3]);
        d0 = f2fma(s[4], kk[4], d0);
        d1 = f2fma(s[5], kk[5], d1);
        d2 = f2fma(s[6], kk[6], d2);
        d3 = f2fma(s[7], kk[7], d3);
        d0 = f2add(d0, d1); d2 = f2add(d2, d3); d0 = f2add(d0, d2);
        float rr = d0.x + d0.y;
        rr += __shfl_xor_sync(0xffffffffu, rr, 1);
        rr += __shfl_xor_sync(0xffffffffu, rr, 2);

        const float gt   = sigmoidf_fast(__fmaf_rn(dg, rr, bg));
        const float beta = (1.0f - a_i) * v_i * gt;   // (1-alpha)*v_gated
        const float2 av = f2dup(a_i);
        const float2 bv = f2dup(beta);

        // S row update: s = alpha*s + beta*k
        #pragma unroll
        for (int m = 0; m < 8; m++)
            s[m] = f2fma(av, s[m], f2mul(bv, kk[m]));

        // out_i = s_new . q
        float2 o0 = f2mul(s[0], qq[0]);
        float2 o1 = f2mul(s[1], qq[1]);
        float2 o2 = f2mul(s[2], qq[2]);
        float2 o3 = f2mul(s[3], qq[3]);
        o0 = f2fma(s[4], qq[4], o0);
        o1 = f2fma(s[5], qq[5], o1);
        o2 = f2fma(s[6], qq[6], o2);
        o3 = f2fma(s[7], qq[7], o3);
        o0 = f2add(o0, o1); o2 = f2add(o2, o3); o0 = f2add(o0, o2);
        float oo = o0.x + o0.y;
        oo += __shfl_xor_sync(0xffffffffu, oo, 1);
        oo += __shfl_xor_sync(0xffffffffu, oo, 2);

        if (c == 0) {
            float sg = sigmoidf_fast(oo);          // out * silu(out) = out^2 * sigmoid(out)
            out[((size_t)t * BATCH + b) * NST + i] = oo * oo * sg;
        }
    }

    // write S_final
    float* fp = &Sfin[(size_t)(b * NST + i) * NST + c * 16];
    #pragma unroll
    for (int m = 0; m < 4; m++) {
        float4 v = make_float4(s[2*m].x, s[2*m].y, s[2*m+1].x, s[2*m+1].y);
        reinterpret_cast<float4*>(fp)[m] = v;
    }
}

// ============================================================================
extern "C" void kernel_launch(void* const* d_in, const int* in_sizes, int n_in,
                              void* d_out, int out_size) {
    const float* x   = (const float*)d_in[0];
    const float* S0  = (const float*)d_in[1];
    const float* Wk  = (const float*)d_in[2];
    const float* Wv  = (const float*)d_in[3];
    const float* Wq  = (const float*)d_in[4];
    const float* Wa  = (const float*)d_in[5];
    const float* ba  = (const float*)d_in[6];
    const float* dg  = (const float*)d_in[7];
    const float* bg  = (const float*)d_in[8];

    float* out  = (float*)d_out;                         // [T,B,N]
    float* Sfin = out + (size_t)T_STEPS * BATCH * NST;   // [B,N,N]

    dim3 g1(M_ROWS / BM, 4);
    proj_kernel<<<g1, 256>>>(x, Wk, Wq, Wv, Wa, ba);
    scan_kernel<<<64, 32>>>(S0, dg, bg, out, Sfin);
}

// round 2
// speedup vs baseline: 1.2303x; 1.2303x over previous
#include <cuda_runtime.h>
#include <cstdint>
#include <cstring>

#define T_STEPS 2048
#define BATCH   8
#define DIMK    1024
#define NST     64
#define M_ROWS  (T_STEPS * BATCH)
#define NCOL    256

// 16 MB scratch: projections, layout [t*BATCH+b][ k(0:64) | q(64:128) | v(128:192) | alpha(192:256) ]
__device__ __align__(16) float g_proj[(size_t)M_ROWS * NCOL];

union F2U { float2 f2; unsigned long long u; };

__device__ __forceinline__ float2 f2fma(float2 a, float2 b, float2 c) {
    F2U ua, ub, uc, ud; ua.f2 = a; ub.f2 = b; uc.f2 = c;
    asm("fma.rn.f32x2 %0, %1, %2, %3;" : "=l"(ud.u) : "l"(ua.u), "l"(ub.u), "l"(uc.u));
    return ud.f2;
}
__device__ __forceinline__ float2 f2mul(float2 a, float2 b) {
    F2U ua, ub, ud; ua.f2 = a; ub.f2 = b;
    asm("mul.rn.f32x2 %0, %1, %2;" : "=l"(ud.u) : "l"(ua.u), "l"(ub.u));
    return ud.f2;
}
__device__ __forceinline__ float2 f2add(float2 a, float2 b) {
    F2U ua, ub, ud; ua.f2 = a; ub.f2 = b;
    asm("add.rn.f32x2 %0, %1, %2;" : "=l"(ud.u) : "l"(ua.u), "l"(ub.u));
    return ud.f2;
}
__device__ __forceinline__ float2 f2dup(float a) {
    F2U ud;
    asm("mov.b64 %0, {%1, %1};" : "=l"(ud.u) : "f"(a));
    return ud.f2;
}
__device__ __forceinline__ float sigmoidf_fast(float x) {
    return __fdividef(1.0f, 1.0f + __expf(-x));
}

// ============================================================================
// Kernel 1: fused projection GEMM. C[m][n] = sum_d x[m][d] * W_sel[n][d]
// blockIdx.y selects which weight matrix (0:k 1:q 2:v 3:alpha).
// ============================================================================
#define BM 128
#define BN 64
#define BK 16

__global__ void __launch_bounds__(256) proj_kernel(
    const float* __restrict__ x,
    const float* __restrict__ Wk, const float* __restrict__ Wq,
    const float* __restrict__ Wv, const float* __restrict__ Wa,
    const float* __restrict__ b_alpha)
{
    __shared__ __align__(16) float As[BK][BM + 4];
    __shared__ __align__(16) float Bs[BK][BN + 4];

    const int tid = threadIdx.x;
    const int m0  = blockIdx.x * BM;
    const int sel = blockIdx.y;
    const float* W = (sel == 0) ? Wk : (sel == 1) ? Wq : (sel == 2) ? Wv : Wa;

    const int ty = tid >> 4;         // 0..15 -> 8 rows each
    const int tx = tid & 15;         // 0..15 -> 4 cols each

    const int lrow = tid >> 2;       // 0..63
    const int lcol = (tid & 3) * 4;  // 0,4,8,12

    float2 acc[4][4];
    #pragma unroll
    for (int ip = 0; ip < 4; ip++)
        #pragma unroll
        for (int j = 0; j < 4; j++) acc[ip][j] = make_float2(0.f, 0.f);

    for (int k0 = 0; k0 < DIMK; k0 += BK) {
        #pragma unroll
        for (int half = 0; half < 2; half++) {
            int r = lrow + half * 64;
            float4 v = *reinterpret_cast<const float4*>(&x[(size_t)(m0 + r) * DIMK + k0 + lcol]);
            As[lcol + 0][r] = v.x; As[lcol + 1][r] = v.y;
            As[lcol + 2][r] = v.z; As[lcol + 3][r] = v.w;
        }
        {
            float4 v = *reinterpret_cast<const float4*>(&W[(size_t)lrow * DIMK + k0 + lcol]);
            Bs[lcol + 0][lrow] = v.x; Bs[lcol + 1][lrow] = v.y;
            Bs[lcol + 2][lrow] = v.z; Bs[lcol + 3][lrow] = v.w;
        }
        __syncthreads();
        #pragma unroll
        for (int k = 0; k < BK; k++) {
            float4 a0 = *reinterpret_cast<const float4*>(&As[k][ty * 8]);
            float4 a1 = *reinterpret_cast<const float4*>(&As[k][ty * 8 + 4]);
            float4 bv = *reinterpret_cast<const float4*>(&Bs[k][tx * 4]);
            float2 a2[4] = { make_float2(a0.x, a0.y), make_float2(a0.z, a0.w),
                             make_float2(a1.x, a1.y), make_float2(a1.z, a1.w) };
            float2 bd[4] = { f2dup(bv.x), f2dup(bv.y), f2dup(bv.z), f2dup(bv.w) };
            #pragma unroll
            for (int ip = 0; ip < 4; ip++)
                #pragma unroll
                for (int j = 0; j < 4; j++)
                    acc[ip][j] = f2fma(a2[ip], bd[j], acc[ip][j]);
        }
        __syncthreads();
    }

    // epilogue: rows ty*8 + 2*ip + h, cols tx*4 + j
    #pragma unroll
    for (int ip = 0; ip < 4; ip++) {
        #pragma unroll
        for (int h = 0; h < 2; h++) {
            int r = ty * 8 + ip * 2 + h;
            float4 o;
            o.x = h ? acc[ip][0].y : acc[ip][0].x;
            o.y = h ? acc[ip][1].y : acc[ip][1].x;
            o.z = h ? acc[ip][2].y : acc[ip][2].x;
            o.w = h ? acc[ip][3].y : acc[ip][3].x;
            if (sel == 3) {  // alpha = sigmoid(proj + b_alpha)
                o.x = sigmoidf_fast(o.x + b_alpha[tx * 4 + 0]);
                o.y = sigmoidf_fast(o.y + b_alpha[tx * 4 + 1]);
                o.z = sigmoidf_fast(o.z + b_alpha[tx * 4 + 2]);
                o.w = sigmoidf_fast(o.w + b_alpha[tx * 4 + 3]);
            }
            *reinterpret_cast<float4*>(&g_proj[(size_t)(m0 + r) * NCOL + sel * 64 + tx * 4]) = o;
        }
    }
}

// ============================================================================
// Kernel 2: sequential scan, critical-path-minimized.
//   out_i = alpha_i*(S_old_i . q) + beta_i*(k . q),  beta_i = (1-alpha_i)*v_i*g_i
// All three dots (s.k, s.q, k.q) are computed BEFORE the sigmoid; their shfl
// reductions overlap. Next-step operands are register-prefetched from the
// cp.async smem ring. The self-gate (out*silu(out)) is applied in a separate
// elementwise pass, keeping the loop free of the trailing MUFU chain.
// ============================================================================
#define DPF 8   // ring slots

__global__ void __launch_bounds__(32) scan_kernel(
    const float* __restrict__ S0,
    const float* __restrict__ d_g,
    const float* __restrict__ b_g,
    float* __restrict__ out,     // [T,B,N]  (raw pre-gate values)
    float* __restrict__ Sfin)    // [B,N,N]
{
    __shared__ __align__(16) float buf[DPF][NCOL];

    const int w    = blockIdx.x;
    const int b    = w >> 3;
    const int gr   = w & 7;
    const int lane = threadIdx.x;
    const int r    = lane >> 2;
    const int c    = lane & 3;
    const int i    = gr * 8 + r;      // global row 0..63

    // sigmoid(d*x+b) = 1/(1+exp2(-(d*x+b)*log2e)) : fold constants
    const float dgl = -d_g[i] * 1.4426950408889634f;
    const float bgl = -b_g[i] * 1.4426950408889634f;

    float2 s[8];
    {
        const float4* sp = reinterpret_cast<const float4*>(&S0[(size_t)(b * NST + i) * NST + c * 16]);
        #pragma unroll
        for (int m = 0; m < 4; m++) {
            float4 v = sp[m];
            s[2*m]   = make_float2(v.x, v.y);
            s[2*m+1] = make_float2(v.z, v.w);
        }
    }

    const int loff = lane * 4;
    const uint32_t sbase = (uint32_t)__cvta_generic_to_shared(&buf[0][0]);

    // prologue: fetch steps 0..DPF-2 into slots 0..DPF-2 (one group each)
    #pragma unroll
    for (int d = 0; d < DPF - 1; d++) {
        const float* src = &g_proj[((size_t)d * BATCH + b) * NCOL + loff];
        uint32_t sa = sbase + (uint32_t)(d * NCOL + loff) * 4u;
        asm volatile(
            "cp.async.ca.shared.global [%0], [%1], 16;\n\t"
            "cp.async.ca.shared.global [%2], [%3], 16;\n\t"
            :: "r"(sa), "l"(src), "r"(sa + 512u), "l"(src + 128));
        asm volatile("cp.async.commit_group;");
    }
    // slot 0 ready (completed >= 1 group)
    asm volatile("cp.async.wait_group %0;" :: "n"(DPF - 2));
    __syncthreads();

    // preload step-0 operands into registers
    float2 kk[8], qq[8];
    float v_i, a_i;
    {
        const float* p = &buf[0][0];
        const float4* kp = reinterpret_cast<const float4*>(p + c * 16);
        const float4* qp = reinterpret_cast<const float4*>(p + 64 + c * 16);
        #pragma unroll
        for (int m = 0; m < 4; m++) {
            float4 v = kp[m];
            kk[2*m] = make_float2(v.x, v.y); kk[2*m+1] = make_float2(v.z, v.w);
            float4 u = qp[m];
            qq[2*m] = make_float2(u.x, u.y); qq[2*m+1] = make_float2(u.z, u.w);
        }
        v_i = p[128 + i];
        a_i = p[192 + i];
    }

    for (int t = 0; t < T_STEPS; t++) {
        // ---- issue prefetch for step t+DPF-1 into slot (t-1)&7 ----
        {
            int tf = t + DPF - 1;
            if (tf > T_STEPS - 1) tf = T_STEPS - 1;
            int slot = tf & (DPF - 1);
            const float* src = &g_proj[((size_t)tf * BATCH + b) * NCOL + loff];
            uint32_t sa = sbase + (uint32_t)(slot * NCOL + loff) * 4u;
            asm volatile(
                "cp.async.ca.shared.global [%0], [%1], 16;\n\t"
                "cp.async.ca.shared.global [%2], [%3], 16;\n\t"
                :: "r"(sa), "l"(src), "r"(sa + 512u), "l"(src + 128));
            asm volatile("cp.async.commit_group;");
        }
        // committed = (DPF-1) + (t+1); allow DPF-2 pending -> slots 0..t+1 done
        asm volatile("cp.async.wait_group %0;" :: "n"(DPF - 2));
        __syncthreads();

        // ---- register-prefetch step t+1 operands (latency hides under compute) ----
        float2 kn[8], qn[8];
        float v_n, a_n;
        {
            int tn = (t + 1 < T_STEPS) ? (t + 1) : t;
            const float* p = &buf[tn & (DPF - 1)][0];
            const float4* kp = reinterpret_cast<const float4*>(p + c * 16);
            const float4* qp = reinterpret_cast<const float4*>(p + 64 + c * 16);
            #pragma unroll
            for (int m = 0; m < 4; m++) {
                float4 v = kp[m];
                kn[2*m] = make_float2(v.x, v.y); kn[2*m+1] = make_float2(v.z, v.w);
                float4 u = qp[m];
                qn[2*m] = make_float2(u.x, u.y); qn[2*m+1] = make_float2(u.z, u.w);
            }
            v_n = p[128 + i];
            a_n = p[192 + i];
        }

        // ---- three dots, all independent of the sigmoid ----
        // rk = s.k, rq = s.q, kq = k.q  (partials over this lane's 16 elems)
        float2 rk0 = f2mul(s[0], kk[0]);
        float2 rk1 = f2mul(s[1], kk[1]);
        float2 rk2 = f2mul(s[2], kk[2]);
        float2 rk3 = f2mul(s[3], kk[3]);
        rk0 = f2fma(s[4], kk[4], rk0);
        rk1 = f2fma(s[5], kk[5], rk1);
        rk2 = f2fma(s[6], kk[6], rk2);
        rk3 = f2fma(s[7], kk[7], rk3);

        float2 rq0 = f2mul(s[0], qq[0]);
        float2 rq1 = f2mul(s[1], qq[1]);
        float2 rq2 = f2mul(s[2], qq[2]);
        float2 rq3 = f2mul(s[3], qq[3]);
        rq0 = f2fma(s[4], qq[4], rq0);
        rq1 = f2fma(s[5], qq[5], rq1);
        rq2 = f2fma(s[6], qq[6], rq2);
        rq3 = f2fma(s[7], qq[7], rq3);

        float2 kq0 = f2mul(kk[0], qq[0]);
        float2 kq1 = f2mul(kk[1], qq[1]);
        float2 kq2 = f2mul(kk[2], qq[2]);
        float2 kq3 = f2mul(kk[3], qq[3]);
        kq0 = f2fma(kk[4], qq[4], kq0);
        kq1 = f2fma(kk[5], qq[5], kq1);
        kq2 = f2fma(kk[6], qq[6], kq2);
        kq3 = f2fma(kk[7], qq[7], kq3);

        rk0 = f2add(rk0, rk1); rk2 = f2add(rk2, rk3); rk0 = f2add(rk0, rk2);
        rq0 = f2add(rq0, rq1); rq2 = f2add(rq2, rq3); rq0 = f2add(rq0, rq2);
        kq0 = f2add(kq0, kq1); kq2 = f2add(kq2, kq3); kq0 = f2add(kq0, kq2);

        float rk = rk0.x + rk0.y;
        float rq = rq0.x + rq0.y;
        float kq = kq0.x + kq0.y;

        // overlapped butterfly reductions over the 4 lanes of this row
        rk += __shfl_xor_sync(0xffffffffu, rk, 1);
        rq += __shfl_xor_sync(0xffffffffu, rq, 1);
        kq += __shfl_xor_sync(0xffffffffu, kq, 1);
        rk += __shfl_xor_sync(0xffffffffu, rk, 2);
        rq += __shfl_xor_sync(0xffffffffu, rq, 2);
        kq += __shfl_xor_sync(0xffffffffu, kq, 2);

        // scalars computable while shfls/sigmoid are in flight
        const float cvi = (1.0f - a_i) * v_i;   // (1-alpha)*v
        const float arq = a_i * rq;

        // g = sigmoid(d*rk + b): FMA -> EX2 -> ADD -> RCP
        float e;
        asm("ex2.approx.f32 %0, %1;" : "=f"(e) : "f"(__fmaf_rn(dgl, rk, bgl)));
        float gt;
        asm("rcp.approx.f32 %0, %1;" : "=f"(gt) : "f"(1.0f + e));

        const float beta = cvi * gt;
        const float2 av = f2dup(a_i);
        const float2 bv = f2dup(beta);

        // S row update: s = alpha*s + beta*k   (the only carried dependency)
        #pragma unroll
        for (int m = 0; m < 8; m++)
            s[m] = f2fma(av, s[m], f2mul(bv, kk[m]));

        // raw output (self-gate applied in a later pass)
        if (c == 0)
            out[((size_t)t * BATCH + b) * NST + i] = __fmaf_rn(beta, kq, arq);

        // rotate prefetched operands
        #pragma unroll
        for (int m = 0; m < 8; m++) { kk[m] = kn[m]; qq[m] = qn[m]; }
        v_i = v_n; a_i = a_n;
    }

    // write S_final
    float* fp = &Sfin[(size_t)(b * NST + i) * NST + c * 16];
    #pragma unroll
    for (int m = 0; m < 4; m++) {
        float4 v = make_float4(s[2*m].x, s[2*m].y, s[2*m+1].x, s[2*m+1].y);
        reinterpret_cast<float4*>(fp)[m] = v;
    }
}

// ============================================================================
// Kernel 3: apply self-gate y = x * silu(x) = x^2 * sigmoid(x) over out[T,B,N]
// ============================================================================
__global__ void __launch_bounds__(256) gate_kernel(float* __restrict__ out)
{
    int idx = blockIdx.x * 1024 + threadIdx.x * 4;
    float4 v = *reinterpret_cast<float4*>(&out[idx]);
    v.x = v.x * v.x * sigmoidf_fast(v.x);
    v.y = v.y * v.y * sigmoidf_fast(v.y);
    v.z = v.z * v.z * sigmoidf_fast(v.z);
    v.w = v.w * v.w * sigmoidf_fast(v.w);
    *reinterpret_cast<float4*>(&out[idx]) = v;
}

// ============================================================================
extern "C" void kernel_launch(void* const* d_in, const int* in_sizes, int n_in,
                              void* d_out, int out_size) {
    const float* x   = (const float*)d_in[0];
    const float* S0  = (const float*)d_in[1];
    const float* Wk  = (const float*)d_in[2];
    const float* Wv  = (const float*)d_in[3];
    const float* Wq  = (const float*)d_in[4];
    const float* Wa  = (const float*)d_in[5];
    const float* ba  = (const float*)d_in[6];
    const float* dg  = (const float*)d_in[7];
    const float* bg  = (const float*)d_in[8];

    float* out  = (float*)d_out;                         // [T,B,N]
    float* Sfin = out + (size_t)T_STEPS * BATCH * NST;   // [B,N,N]

    dim3 g1(M_ROWS / BM, 4);
    proj_kernel<<<g1, 256>>>(x, Wk, Wq, Wv, Wa, ba);
    scan_kernel<<<64, 32>>>(S0, dg, bg, out, Sfin);
    gate_kernel<<<(T_STEPS * BATCH * NST) / 1024, 256>>>(out);
}

// round 3
// speedup vs baseline: 1.4174x; 1.1522x over previous
#include <cuda_runtime.h>
#include <cstdint>
#include <cstring>

#define T_STEPS 2048
#define BATCH   8
#define DIMK    1024
#define NST     64
#define M_ROWS  (T_STEPS * BATCH)
#define NCOL    256

// 16 MB scratch: projections, layout [t*BATCH+b][ k(0:64) | q(64:128) | v(128:192) | alpha(192:256) ]
__device__ __align__(16) float g_proj[(size_t)M_ROWS * NCOL];

union F2U { float2 f2; unsigned long long u; };

__device__ __forceinline__ float2 f2fma(float2 a, float2 b, float2 c) {
    F2U ua, ub, uc, ud; ua.f2 = a; ub.f2 = b; uc.f2 = c;
    asm("fma.rn.f32x2 %0, %1, %2, %3;" : "=l"(ud.u) : "l"(ua.u), "l"(ub.u), "l"(uc.u));
    return ud.f2;
}
__device__ __forceinline__ float2 f2mul(float2 a, float2 b) {
    F2U ua, ub, ud; ua.f2 = a; ub.f2 = b;
    asm("mul.rn.f32x2 %0, %1, %2;" : "=l"(ud.u) : "l"(ua.u), "l"(ub.u));
    return ud.f2;
}
__device__ __forceinline__ float2 f2add(float2 a, float2 b) {
    F2U ua, ub, ud; ua.f2 = a; ub.f2 = b;
    asm("add.rn.f32x2 %0, %1, %2;" : "=l"(ud.u) : "l"(ua.u), "l"(ub.u));
    return ud.f2;
}
__device__ __forceinline__ float2 f2dup(float a) {
    F2U ud;
    asm("mov.b64 %0, {%1, %1};" : "=l"(ud.u) : "f"(a));
    return ud.f2;
}
__device__ __forceinline__ float sigmoidf_fast(float x) {
    return __fdividef(1.0f, 1.0f + __expf(-x));
}

// ============================================================================
// Kernel 1: fused projection GEMM. C[m][n] = sum_d x[m][d] * W_sel[n][d]
// blockIdx.y selects which weight matrix (0:k 1:q 2:v 3:alpha).
// ============================================================================
#define BM 128
#define BN 64
#define BK 16

__global__ void __launch_bounds__(256) proj_kernel(
    const float* __restrict__ x,
    const float* __restrict__ Wk, const float* __restrict__ Wq,
    const float* __restrict__ Wv, const float* __restrict__ Wa,
    const float* __restrict__ b_alpha)
{
    __shared__ __align__(16) float As[BK][BM + 4];
    __shared__ __align__(16) float Bs[BK][BN + 4];

    const int tid = threadIdx.x;
    const int m0  = blockIdx.x * BM;
    const int sel = blockIdx.y;
    const float* W = (sel == 0) ? Wk : (sel == 1) ? Wq : (sel == 2) ? Wv : Wa;

    const int ty = tid >> 4;         // 0..15 -> 8 rows each
    const int tx = tid & 15;         // 0..15 -> 4 cols each

    const int lrow = tid >> 2;       // 0..63
    const int lcol = (tid & 3) * 4;  // 0,4,8,12

    float2 acc[4][4];
    #pragma unroll
    for (int ip = 0; ip < 4; ip++)
        #pragma unroll
        for (int j = 0; j < 4; j++) acc[ip][j] = make_float2(0.f, 0.f);

    for (int k0 = 0; k0 < DIMK; k0 += BK) {
        #pragma unroll
        for (int half = 0; half < 2; half++) {
            int r = lrow + half * 64;
            float4 v = *reinterpret_cast<const float4*>(&x[(size_t)(m0 + r) * DIMK + k0 + lcol]);
            As[lcol + 0][r] = v.x; As[lcol + 1][r] = v.y;
            As[lcol + 2][r] = v.z; As[lcol + 3][r] = v.w;
        }
        {
            float4 v = *reinterpret_cast<const float4*>(&W[(size_t)lrow * DIMK + k0 + lcol]);
            Bs[lcol + 0][lrow] = v.x; Bs[lcol + 1][lrow] = v.y;
            Bs[lcol + 2][lrow] = v.z; Bs[lcol + 3][lrow] = v.w;
        }
        __syncthreads();
        #pragma unroll
        for (int k = 0; k < BK; k++) {
            float4 a0 = *reinterpret_cast<const float4*>(&As[k][ty * 8]);
            float4 a1 = *reinterpret_cast<const float4*>(&As[k][ty * 8 + 4]);
            float4 bv = *reinterpret_cast<const float4*>(&Bs[k][tx * 4]);
            float2 a2[4] = { make_float2(a0.x, a0.y), make_float2(a0.z, a0.w),
                             make_float2(a1.x, a1.y), make_float2(a1.z, a1.w) };
            float2 bd[4] = { f2dup(bv.x), f2dup(bv.y), f2dup(bv.z), f2dup(bv.w) };
            #pragma unroll
            for (int ip = 0; ip < 4; ip++)
                #pragma unroll
                for (int j = 0; j < 4; j++)
                    acc[ip][j] = f2fma(a2[ip], bd[j], acc[ip][j]);
        }
        __syncthreads();
    }

    // epilogue: rows ty*8 + 2*ip + h, cols tx*4 + j
    #pragma unroll
    for (int ip = 0; ip < 4; ip++) {
        #pragma unroll
        for (int h = 0; h < 2; h++) {
            int r = ty * 8 + ip * 2 + h;
            float4 o;
            o.x = h ? acc[ip][0].y : acc[ip][0].x;
            o.y = h ? acc[ip][1].y : acc[ip][1].x;
            o.z = h ? acc[ip][2].y : acc[ip][2].x;
            o.w = h ? acc[ip][3].y : acc[ip][3].x;
            if (sel == 3) {  // alpha = sigmoid(proj + b_alpha)
                o.x = sigmoidf_fast(o.x + b_alpha[tx * 4 + 0]);
                o.y = sigmoidf_fast(o.y + b_alpha[tx * 4 + 1]);
                o.z = sigmoidf_fast(o.z + b_alpha[tx * 4 + 2]);
                o.w = sigmoidf_fast(o.w + b_alpha[tx * 4 + 3]);
            }
            *reinterpret_cast<float4*>(&g_proj[(size_t)(m0 + r) * NCOL + sel * 64 + tx * 4]) = o;
        }
    }
}

// ============================================================================
// Kernel 2: sequential scan.
// 128 blocks x 32 threads; 4 rows per warp, 8 lanes per row, 8 state elems
// (4 x f32x2) per lane. Deferred output: out(t-1) = S_t . q_{t-1} is computed
// at the top of iter t from the freshly-updated state, so only TWO dots on s
// per step (s.k_t and s.q_{t-1}); their shfl reductions overlap.
// ============================================================================
#define DPF 8   // ring slots

__global__ void __launch_bounds__(32) scan_kernel(
    const float* __restrict__ S0,
    const float* __restrict__ d_g,
    const float* __restrict__ b_g,
    float* __restrict__ out,     // [T,B,N]  (raw pre-gate values)
    float* __restrict__ Sfin)    // [B,N,N]
{
    __shared__ __align__(16) float buf[DPF][NCOL];

    const int bx   = blockIdx.x;
    const int b    = bx >> 4;          // batch 0..7
    const int rg   = bx & 15;          // row group 0..15
    const int lane = threadIdx.x;
    const int r    = lane >> 3;        // row within group 0..3
    const int c    = lane & 7;         // column slice 0..7 (8 elems each)
    const int i    = rg * 4 + r;       // global row 0..63

    // sigmoid(d*x+b) = 1/(1+exp2(-(d*x+b)*log2e)) : fold constants
    const float dgl = -d_g[i] * 1.4426950408889634f;
    const float bgl = -b_g[i] * 1.4426950408889634f;

    // state: 8 elems per lane = 4 x f32x2
    float2 s[4];
    {
        const float4* sp = reinterpret_cast<const float4*>(&S0[(size_t)(b * NST + i) * NST + c * 8]);
        float4 v0 = sp[0], v1 = sp[1];
        s[0] = make_float2(v0.x, v0.y); s[1] = make_float2(v0.z, v0.w);
        s[2] = make_float2(v1.x, v1.y); s[3] = make_float2(v1.z, v1.w);
    }

    const uint32_t sbase = (uint32_t)__cvta_generic_to_shared(&buf[0][0]);
    const int loff = lane * 8;   // floats

    // prologue: fetch steps 0..DPF-2 into slots 0..DPF-2 (one group each)
    #pragma unroll
    for (int d = 0; d < DPF - 1; d++) {
        const float* src = &g_proj[((size_t)d * BATCH + b) * NCOL + loff];
        uint32_t sa = sbase + (uint32_t)(d * NCOL + loff) * 4u;
        asm volatile(
            "cp.async.ca.shared.global [%0], [%1], 16;\n\t"
            "cp.async.ca.shared.global [%2], [%3], 16;\n\t"
            :: "r"(sa), "l"(src), "r"(sa + 16u), "l"(src + 4));
        asm volatile("cp.async.commit_group;");
    }
    asm volatile("cp.async.wait_group %0;" :: "n"(DPF - 2));
    __syncwarp();

    // load step-0 operands
    float2 kk[4], qq[4], qp[4];
    float v_i, a_i;
    {
        const float* p = &buf[0][0];
        float4 kv0 = *reinterpret_cast<const float4*>(p + c * 8);
        float4 kv1 = *reinterpret_cast<const float4*>(p + c * 8 + 4);
        float4 qv0 = *reinterpret_cast<const float4*>(p + 64 + c * 8);
        float4 qv1 = *reinterpret_cast<const float4*>(p + 64 + c * 8 + 4);
        kk[0] = make_float2(kv0.x, kv0.y); kk[1] = make_float2(kv0.z, kv0.w);
        kk[2] = make_float2(kv1.x, kv1.y); kk[3] = make_float2(kv1.z, kv1.w);
        qq[0] = make_float2(qv0.x, qv0.y); qq[1] = make_float2(qv0.z, qv0.w);
        qq[2] = make_float2(qv1.x, qv1.y); qq[3] = make_float2(qv1.z, qv1.w);
        v_i = p[128 + i];
        a_i = p[192 + i];
    }
    #pragma unroll
    for (int m = 0; m < 4; m++) qp[m] = make_float2(0.f, 0.f);

    for (int t = 0; t < T_STEPS; t++) {
        // ---- issue prefetch for step t+DPF-1 ----
        {
            int tf = t + DPF - 1;
            if (tf > T_STEPS - 1) tf = T_STEPS - 1;
            int slot = tf & (DPF - 1);
            const float* src = &g_proj[((size_t)tf * BATCH + b) * NCOL + loff];
            uint32_t sa = sbase + (uint32_t)(slot * NCOL + loff) * 4u;
            asm volatile(
                "cp.async.ca.shared.global [%0], [%1], 16;\n\t"
                "cp.async.ca.shared.global [%2], [%3], 16;\n\t"
                :: "r"(sa), "l"(src), "r"(sa + 16u), "l"(src + 4));
            asm volatile("cp.async.commit_group;");
        }
        asm volatile("cp.async.wait_group %0;" :: "n"(DPF - 2));
        __syncwarp();

        // ---- register-prefetch step t+1 operands ----
        float2 kn[4], qn[4];
        float v_n, a_n;
        {
            int tn = (t + 1 < T_STEPS) ? (t + 1) : t;
            const float* p = &buf[tn & (DPF - 1)][0];
            float4 kv0 = *reinterpret_cast<const float4*>(p + c * 8);
            float4 kv1 = *reinterpret_cast<const float4*>(p + c * 8 + 4);
            float4 qv0 = *reinterpret_cast<const float4*>(p + 64 + c * 8);
            float4 qv1 = *reinterpret_cast<const float4*>(p + 64 + c * 8 + 4);
            kn[0] = make_float2(kv0.x, kv0.y); kn[1] = make_float2(kv0.z, kv0.w);
            kn[2] = make_float2(kv1.x, kv1.y); kn[3] = make_float2(kv1.z, kv1.w);
            qn[0] = make_float2(qv0.x, qv0.y); qn[1] = make_float2(qv0.z, qv0.w);
            qn[2] = make_float2(qv1.x, qv1.y); qn[3] = make_float2(qv1.z, qv1.w);
            v_n = p[128 + i];
            a_n = p[192 + i];
        }

        // ---- two dots on s: rk = s.k_t (feeds sigmoid), oq = s.q_{t-1} = out(t-1)
        float2 ra = f2mul(s[0], kk[0]);
        float2 rb = f2mul(s[1], kk[1]);
        float2 oa = f2mul(s[0], qp[0]);
        float2 ob = f2mul(s[1], qp[1]);
        ra = f2fma(s[2], kk[2], ra);
        rb = f2fma(s[3], kk[3], rb);
        oa = f2fma(s[2], qp[2], oa);
        ob = f2fma(s[3], qp[3], ob);
        ra = f2add(ra, rb);
        oa = f2add(oa, ob);
        float rk = ra.x + ra.y;
        float oq = oa.x + oa.y;

        // overlapped butterfly reductions over the 8 lanes of this row
        rk += __shfl_xor_sync(0xffffffffu, rk, 1);
        oq += __shfl_xor_sync(0xffffffffu, oq, 1);
        rk += __shfl_xor_sync(0xffffffffu, rk, 2);
        oq += __shfl_xor_sync(0xffffffffu, oq, 2);
        rk += __shfl_xor_sync(0xffffffffu, rk, 4);
        oq += __shfl_xor_sync(0xffffffffu, oq, 4);

        const float cvi = (1.0f - a_i) * v_i;   // off the sigmoid path

        // g = sigmoid(d*rk + b): FMA -> EX2 -> ADD -> RCP
        float e;
        asm("ex2.approx.f32 %0, %1;" : "=f"(e) : "f"(__fmaf_rn(dgl, rk, bgl)));
        float gt;
        asm("rcp.approx.f32 %0, %1;" : "=f"(gt) : "f"(1.0f + e));

        const float beta = cvi * gt;
        const float2 av = f2dup(a_i);
        const float2 bv = f2dup(beta);

        // S row update: s = alpha*s + beta*k   (the only carried dependency)
        #pragma unroll
        for (int m = 0; m < 4; m++)
            s[m] = f2fma(av, s[m], f2mul(bv, kk[m]));

        // store out(t-1)  (raw; self-gate applied in a later pass)
        if (t > 0 && c == 0)
            out[((size_t)(t - 1) * BATCH + b) * NST + i] = oq;

        // rotate operands
        #pragma unroll
        for (int m = 0; m < 4; m++) { qp[m] = qq[m]; kk[m] = kn[m]; qq[m] = qn[m]; }
        v_i = v_n; a_i = a_n;
    }

    // final output: out(T-1) = S_T . q_{T-1}   (qp holds q_{T-1} after loop)
    {
        float2 oa = f2mul(s[0], qp[0]);
        float2 ob = f2mul(s[1], qp[1]);
        oa = f2fma(s[2], qp[2], oa);
        ob = f2fma(s[3], qp[3], ob);
        oa = f2add(oa, ob);
        float oq = oa.x + oa.y;
        oq += __shfl_xor_sync(0xffffffffu, oq, 1);
        oq += __shfl_xor_sync(0xffffffffu, oq, 2);
        oq += __shfl_xor_sync(0xffffffffu, oq, 4);
        if (c == 0)
            out[((size_t)(T_STEPS - 1) * BATCH + b) * NST + i] = oq;
    }

    // write S_final
    float* fp = &Sfin[(size_t)(b * NST + i) * NST + c * 8];
    reinterpret_cast<float4*>(fp)[0] = make_float4(s[0].x, s[0].y, s[1].x, s[1].y);
    reinterpret_cast<float4*>(fp)[1] = make_float4(s[2].x, s[2].y, s[3].x, s[3].y);
}

// ============================================================================
// Kernel 3: apply self-gate y = x * silu(x) = x^2 * sigmoid(x) over out[T,B,N]
// ============================================================================
__global__ void __launch_bounds__(256) gate_kernel(float* __restrict__ out)
{
    int idx = blockIdx.x * 1024 + threadIdx.x * 4;
    float4 v = *reinterpret_cast<float4*>(&out[idx]);
    v.x = v.x * v.x * sigmoidf_fast(v.x);
    v.y = v.y * v.y * sigmoidf_fast(v.y);
    v.z = v.z * v.z * sigmoidf_fast(v.z);
    v.w = v.w * v.w * sigmoidf_fast(v.w);
    *reinterpret_cast<float4*>(&out[idx]) = v;
}

// ============================================================================
extern "C" void kernel_launch(void* const* d_in, const int* in_sizes, int n_in,
                              void* d_out, int out_size) {
    const float* x   = (const float*)d_in[0];
    const float* S0  = (const float*)d_in[1];
    const float* Wk  = (const float*)d_in[2];
    const float* Wv  = (const float*)d_in[3];
    const float* Wq  = (const float*)d_in[4];
    const float* Wa  = (const float*)d_in[5];
    const float* ba  = (const float*)d_in[6];
    const float* dg  = (const float*)d_in[7];
    const float* bg  = (const float*)d_in[8];

    float* out  = (float*)d_out;                         // [T,B,N]
    float* Sfin = out + (size_t)T_STEPS * BATCH * NST;   // [B,N,N]

    dim3 g1(M_ROWS / BM, 4);
    proj_kernel<<<g1, 256>>>(x, Wk, Wq, Wv, Wa, ba);
    scan_kernel<<<128, 32>>>(S0, dg, bg, out, Sfin);
    gate_kernel<<<(T_STEPS * BATCH * NST) / 1024, 256>>>(out);
}